// round 6
// baseline (speedup 1.0000x reference)
#include <cuda_runtime.h>
#include <cuda_fp16.h>
#include <cuda_bf16.h>
#include <cstdint>

#define N_NODES 50000
#define N_EDGES 800000
#define IN_DIM 512
#define HEADS 4
#define OUT_DIM 64
#define HD 256  // HEADS*OUT_DIM

// ---------------- scratch (device globals; no runtime alloc) ----------------
__device__ float  g_h[N_NODES * HD];         // 51.2 MB fp32 features (for scores)
__device__ __half g_h16[N_NODES * HD];       // 25.6 MB fp16 copy (for gather)
__device__ float  g_ssrc[N_NODES * HEADS];
__device__ float  g_sdst[N_NODES * HEADS];
__device__ float  g_e[N_EDGES * HEADS];      // exp values (edge order)
__device__ float  g_sum[N_NODES * HEADS];    // sum -> reciprocal
__device__ int    g_cnt[N_NODES];            // degree counts / fill cursors
__device__ int    g_offs[N_NODES + 1];       // CSR offsets (by dst)
__device__ int    g_part[256];               // scan partials
__device__ int    g_src[N_EDGES];            // src per CSR slot
__device__ float  g_alpha[N_EDGES * HEADS];  // alpha per CSR slot (CSR order)

// ================= TF32 MMA GEMM: h = x @ W  (50000x512 @ 512x256) =========
#define GBM 128
#define GBN 64
#define GBK 32

__device__ __forceinline__ uint32_t f32_to_tf32(float f) {
    uint32_t r;
    asm("cvt.rna.tf32.f32 %0, %1;" : "=r"(r) : "f"(f));
    return r;
}

__global__ __launch_bounds__(256) void gat_gemm_tf32_kernel(
    const float* __restrict__ X, const float* __restrict__ W) {
    __shared__ uint32_t As[GBM][GBK + 4];   // [m][k]
    __shared__ uint32_t Bs[GBK][GBN + 4];   // [k][n]

    const int tid = threadIdx.x;
    const int lane = tid & 31;
    const int warp = tid >> 5;
    const int warp_m = warp >> 1;
    const int warp_n = warp & 1;

    const int bm = blockIdx.x * GBM;
    const int bn = blockIdx.y * GBN;

    float acc[2][4][4];
#pragma unroll
    for (int i = 0; i < 2; i++)
#pragma unroll
        for (int j = 0; j < 4; j++)
#pragma unroll
            for (int r = 0; r < 4; r++) acc[i][j][r] = 0.f;

    const int a_row_in = tid >> 3;
    const int a_k4 = (tid & 7) * 4;
    const int b_k_in = tid >> 4;
    const int b_n4 = (tid & 15) * 4;

    const int lg = lane >> 2;
    const int lt = lane & 3;

    for (int kt = 0; kt < IN_DIM; kt += GBK) {
#pragma unroll
        for (int i = 0; i < 4; i++) {
            int row = a_row_in + i * 32;
            int gm = bm + row;
            float4 v = make_float4(0.f, 0.f, 0.f, 0.f);
            if (gm < N_NODES)
                v = *(const float4*)(X + (size_t)gm * IN_DIM + kt + a_k4);
            As[row][a_k4 + 0] = f32_to_tf32(v.x);
            As[row][a_k4 + 1] = f32_to_tf32(v.y);
            As[row][a_k4 + 2] = f32_to_tf32(v.z);
            As[row][a_k4 + 3] = f32_to_tf32(v.w);
        }
#pragma unroll
        for (int i = 0; i < 2; i++) {
            int k = b_k_in + i * 16;
            float4 v = *(const float4*)(W + (size_t)(kt + k) * HD + bn + b_n4);
            Bs[k][b_n4 + 0] = f32_to_tf32(v.x);
            Bs[k][b_n4 + 1] = f32_to_tf32(v.y);
            Bs[k][b_n4 + 2] = f32_to_tf32(v.z);
            Bs[k][b_n4 + 3] = f32_to_tf32(v.w);
        }
        __syncthreads();

#pragma unroll
        for (int kk = 0; kk < GBK; kk += 8) {
            uint32_t af[2][4];
#pragma unroll
            for (int mt = 0; mt < 2; mt++) {
                int rb = warp_m * 32 + mt * 16;
                af[mt][0] = As[rb + lg][kk + lt];
                af[mt][1] = As[rb + lg + 8][kk + lt];
                af[mt][2] = As[rb + lg][kk + lt + 4];
                af[mt][3] = As[rb + lg + 8][kk + lt + 4];
            }
            uint32_t bf[4][2];
#pragma unroll
            for (int nt = 0; nt < 4; nt++) {
                int cb = warp_n * 32 + nt * 8;
                bf[nt][0] = Bs[kk + lt][cb + lg];
                bf[nt][1] = Bs[kk + lt + 4][cb + lg];
            }
#pragma unroll
            for (int mt = 0; mt < 2; mt++)
#pragma unroll
                for (int nt = 0; nt < 4; nt++) {
                    asm volatile(
                        "mma.sync.aligned.m16n8k8.row.col.f32.tf32.tf32.f32 "
                        "{%0,%1,%2,%3}, {%4,%5,%6,%7}, {%8,%9}, {%0,%1,%2,%3};"
                        : "+f"(acc[mt][nt][0]), "+f"(acc[mt][nt][1]),
                          "+f"(acc[mt][nt][2]), "+f"(acc[mt][nt][3])
                        : "r"(af[mt][0]), "r"(af[mt][1]), "r"(af[mt][2]),
                          "r"(af[mt][3]), "r"(bf[nt][0]), "r"(bf[nt][1]));
                }
        }
        __syncthreads();
    }

#pragma unroll
    for (int mt = 0; mt < 2; mt++) {
#pragma unroll
        for (int nt = 0; nt < 4; nt++) {
            int row0 = bm + warp_m * 32 + mt * 16 + lg;
            int col = bn + warp_n * 32 + nt * 8 + 2 * lt;
            if (row0 < N_NODES) {
                float2 v = make_float2(acc[mt][nt][0], acc[mt][nt][1]);
                *(float2*)&g_h[(size_t)row0 * HD + col] = v;
                *(__half2*)&g_h16[(size_t)row0 * HD + col] =
                    __floats2half2_rn(v.x, v.y);
            }
            int row1 = row0 + 8;
            if (row1 < N_NODES) {
                float2 v = make_float2(acc[mt][nt][2], acc[mt][nt][3]);
                *(float2*)&g_h[(size_t)row1 * HD + col] = v;
                *(__half2*)&g_h16[(size_t)row1 * HD + col] =
                    __floats2half2_rn(v.x, v.y);
            }
        }
    }
}

// ---------------- per-(node,head) attention scores ----------------
__global__ void gat_score_kernel(const float* __restrict__ a) {
    int i = blockIdx.x * blockDim.x + threadIdx.x;
    if (i >= N_NODES * HEADS) return;
    int node = i >> 2;
    int head = i & 3;
    const float* hp = g_h + (size_t)node * HD + head * OUT_DIM;
    const float* asrc = a + head * (2 * OUT_DIM);
    const float* adst = asrc + OUT_DIM;
    float ss = 0.f, sd = 0.f;
#pragma unroll 8
    for (int d = 0; d < OUT_DIM; d++) {
        float hv = hp[d];
        ss += hv * asrc[d];
        sd += hv * adst[d];
    }
    g_ssrc[i] = ss;
    g_sdst[i] = sd;
}

// ---------------- zero counters + sums ----------------
__global__ void gat_zero_kernel() {
    int i = blockIdx.x * blockDim.x + threadIdx.x;
    if (i < N_NODES) g_cnt[i] = 0;
    if (i < N_NODES * HEADS) g_sum[i] = 0.f;
}

// ----- fused edge pass: histogram + leaky_relu + exp + segment sum -------
__global__ void gat_edge_kernel(const int* __restrict__ edges) {
    int e = blockIdx.x * blockDim.x + threadIdx.x;
    if (e >= N_EDGES) return;
    int2 ed = ((const int2*)edges)[e];
    float4 ss = *(const float4*)&g_ssrc[ed.x * HEADS];
    float4 sd = *(const float4*)&g_sdst[ed.y * HEADS];
    float4 v;
    v.x = ss.x + sd.x; v.x = (v.x > 0.f) ? v.x : 0.2f * v.x;
    v.y = ss.y + sd.y; v.y = (v.y > 0.f) ? v.y : 0.2f * v.y;
    v.z = ss.z + sd.z; v.z = (v.z > 0.f) ? v.z : 0.2f * v.z;
    v.w = ss.w + sd.w; v.w = (v.w > 0.f) ? v.w : 0.2f * v.w;
    v.x = __expf(v.x);
    v.y = __expf(v.y);
    v.z = __expf(v.z);
    v.w = __expf(v.w);
    *(float4*)&g_e[e * HEADS] = v;
    float* sp = &g_sum[ed.x * HEADS];
    atomicAdd(sp + 0, v.x);
    atomicAdd(sp + 1, v.y);
    atomicAdd(sp + 2, v.z);
    atomicAdd(sp + 3, v.w);
    atomicAdd(&g_cnt[ed.y], 1);
}

// ---------------- block scan phase 1 (256/block) ----------------
__global__ void gat_scan1_kernel() {
    __shared__ int s[256];
    int t = threadIdx.x;
    int i = blockIdx.x * 256 + t;
    int v = (i < N_NODES) ? g_cnt[i] : 0;
    s[t] = v;
    __syncthreads();
#pragma unroll
    for (int off = 1; off < 256; off <<= 1) {
        int u = (t >= off) ? s[t - off] : 0;
        __syncthreads();
        s[t] += u;
        __syncthreads();
    }
    if (i < N_NODES) g_offs[i] = s[t] - v;
    if (t == 255) g_part[blockIdx.x] = s[255];
}

// ---------------- scan phase 2: scan partials (1 block) ----------------
__global__ void gat_scan2_kernel(int nblk) {
    __shared__ int s[256];
    int t = threadIdx.x;
    int v = (t < nblk) ? g_part[t] : 0;
    s[t] = v;
    __syncthreads();
#pragma unroll
    for (int off = 1; off < 256; off <<= 1) {
        int u = (t >= off) ? s[t - off] : 0;
        __syncthreads();
        s[t] += u;
        __syncthreads();
    }
    g_part[t] = s[t] - v;
}

// ---------------- scan phase 3: add partials, reset cnt ----------------
__global__ void gat_scan3_kernel() {
    int i = blockIdx.x * blockDim.x + threadIdx.x;
    if (i < N_NODES) {
        g_offs[i] += g_part[i >> 8];
        g_cnt[i] = 0;
    }
    if (i == 0) g_offs[N_NODES] = N_EDGES;
}

// ---------------- reciprocal of denominators ----------------
__global__ void gat_rsum_kernel() {
    int i = blockIdx.x * blockDim.x + threadIdx.x;
    if (i >= N_NODES * HEADS) return;
    g_sum[i] = __frcp_rn(g_sum[i] + 1e-10f);
}

// ------- CSR fill + alpha (stored in CSR order) ----------------
__global__ void gat_fill_kernel(const int* __restrict__ edges) {
    int e = blockIdx.x * blockDim.x + threadIdx.x;
    if (e >= N_EDGES) return;
    int2 ed = ((const int2*)edges)[e];
    int pos = g_offs[ed.y] + atomicAdd(&g_cnt[ed.y], 1);
    g_src[pos] = ed.x;
    float4 ex = *(const float4*)&g_e[e * HEADS];
    float4 r = *(const float4*)&g_sum[ed.x * HEADS];
    ex.x *= r.x; ex.y *= r.y; ex.z *= r.z; ex.w *= r.w;
    *(float4*)&g_alpha[(size_t)pos * HEADS] = ex;
}

// ------- aggregation: 32 threads/node, fp16 gather, plain stores -------
__global__ __launch_bounds__(256) void gat_aggregate_kernel(
    float* __restrict__ out, const float* __restrict__ bias) {
    int node = blockIdx.x * 8 + (threadIdx.x >> 5);
    if (node >= N_NODES) return;
    int t = threadIdx.x & 31;     // owns cols [8t, 8t+8)
    int head = t >> 3;

    int beg = g_offs[node];
    int end = g_offs[node + 1];

    float acc[8];
#pragma unroll
    for (int j = 0; j < 8; j++) acc[j] = 0.f;

    int i = beg;
    for (; i + 1 < end; i += 2) {
        int s0 = g_src[i];
        int s1 = g_src[i + 1];
        float a0 = g_alpha[(size_t)i * HEADS + head];
        float a1 = g_alpha[(size_t)(i + 1) * HEADS + head];
        uint4 p0 = *(const uint4*)&g_h16[(size_t)s0 * HD + t * 8];
        uint4 p1 = *(const uint4*)&g_h16[(size_t)s1 * HD + t * 8];
        const __half2* h0 = (const __half2*)&p0;
        const __half2* h1 = (const __half2*)&p1;
#pragma unroll
        for (int j = 0; j < 4; j++) {
            float2 f0 = __half22float2(h0[j]);
            float2 f1 = __half22float2(h1[j]);
            acc[2 * j + 0] += a0 * f0.x + a1 * f1.x;
            acc[2 * j + 1] += a0 * f0.y + a1 * f1.y;
        }
    }
    if (i < end) {
        int s0 = g_src[i];
        float a0 = g_alpha[(size_t)i * HEADS + head];
        uint4 p0 = *(const uint4*)&g_h16[(size_t)s0 * HD + t * 8];
        const __half2* h0 = (const __half2*)&p0;
#pragma unroll
        for (int j = 0; j < 4; j++) {
            float2 f0 = __half22float2(h0[j]);
            acc[2 * j + 0] += a0 * f0.x;
            acc[2 * j + 1] += a0 * f0.y;
        }
    }

    float4 b0 = *(const float4*)&bias[t * 8];
    float4 b1 = *(const float4*)&bias[t * 8 + 4];
    float4 o0 = make_float4(acc[0] + b0.x, acc[1] + b0.y,
                            acc[2] + b0.z, acc[3] + b0.w);
    float4 o1 = make_float4(acc[4] + b1.x, acc[5] + b1.y,
                            acc[6] + b1.z, acc[7] + b1.w);
    *(float4*)&out[(size_t)node * HD + t * 8] = o0;
    *(float4*)&out[(size_t)node * HD + t * 8 + 4] = o1;
}

// ---------------- launch ----------------
extern "C" void kernel_launch(void* const* d_in, const int* in_sizes, int n_in,
                              void* d_out, int out_size) {
    const float* x     = (const float*)d_in[0];
    const int*   edges = (const int*)d_in[1];
    const float* W     = (const float*)d_in[2];
    const float* a     = (const float*)d_in[3];
    const float* bias  = (const float*)d_in[4];
    float* out = (float*)d_out;

    const int nh = N_NODES * HEADS;
    const int nblk_scan = (N_NODES + 255) / 256;  // 196

    gat_zero_kernel<<<(nh + 255) / 256, 256>>>();

    dim3 gemm_grid((N_NODES + GBM - 1) / GBM, HD / GBN);
    gat_gemm_tf32_kernel<<<gemm_grid, 256>>>(x, W);

    gat_score_kernel<<<(nh + 255) / 256, 256>>>(a);
    gat_edge_kernel<<<(N_EDGES + 255) / 256, 256>>>(edges);

    gat_scan1_kernel<<<nblk_scan, 256>>>();
    gat_scan2_kernel<<<1, 256>>>(nblk_scan);
    gat_scan3_kernel<<<nblk_scan, 256>>>();
    gat_rsum_kernel<<<(nh + 255) / 256, 256>>>();
    gat_fill_kernel<<<(N_EDGES + 255) / 256, 256>>>(edges);

    gat_aggregate_kernel<<<(N_NODES + 7) / 8, 256>>>(out, bias);
}

// round 8
// speedup vs baseline: 1.4872x; 1.4872x over previous
#include <cuda_runtime.h>
#include <cuda_fp16.h>
#include <cuda_bf16.h>
#include <cstdint>

#define N_NODES 50000
#define N_EDGES 800000
#define IN_DIM 512
#define HEADS 4
#define OUT_DIM 64
#define HD 256  // HEADS*OUT_DIM

// ---------------- scratch (device globals; no runtime alloc) ----------------
__device__ float  g_h[N_NODES * HD];         // 51.2 MB fp32 features
__device__ __half g_h16[N_NODES * HD];       // 25.6 MB fp16 copy (gather)
__device__ float  g_ssrc[N_NODES * HEADS];
__device__ float  g_sdst[N_NODES * HEADS];
__device__ float  g_e[N_EDGES * HEADS];      // exp values -> alpha (in place)
__device__ float  g_sum[N_NODES * HEADS];    // sum -> reciprocal
__device__ int    g_cnt[N_NODES];
__device__ int    g_offs[N_NODES + 1];
__device__ int    g_part[256];
__device__ int2   g_csr[N_EDGES];            // (src, edge_id) grouped by dst

// ================= TF32 MMA GEMM, double-buffered ==========================
#define GBM 128
#define GBN 64
#define GBK 32
#define NKT (IN_DIM / GBK)   // 16

__device__ __forceinline__ uint32_t f32_to_tf32(float f) {
    uint32_t r;
    asm("cvt.rna.tf32.f32 %0, %1;" : "=r"(r) : "f"(f));
    return r;
}

__global__ __launch_bounds__(256) void gat_gemm_tf32_kernel(
    const float* __restrict__ X, const float* __restrict__ W) {
    __shared__ uint32_t As[2][GBM][GBK + 4];   // [buf][m][k]
    __shared__ uint32_t Bs[2][GBK][GBN + 4];   // [buf][k][n]

    const int tid = threadIdx.x;
    const int lane = tid & 31;
    const int warp = tid >> 5;
    const int warp_m = warp >> 1;
    const int warp_n = warp & 1;

    const int bm = blockIdx.x * GBM;
    const int bn = blockIdx.y * GBN;

    float acc[2][4][4];
#pragma unroll
    for (int i = 0; i < 2; i++)
#pragma unroll
        for (int j = 0; j < 4; j++)
#pragma unroll
            for (int r = 0; r < 4; r++) acc[i][j][r] = 0.f;

    const int a_row_in = tid >> 3;          // 0..31, + i*32
    const int a_k4 = (tid & 7) * 4;
    const int b_k_in = tid >> 4;            // 0..15, + i*16
    const int b_n4 = (tid & 15) * 4;

    const int lg = lane >> 2;
    const int lt = lane & 3;

    // staging registers for the next tile
    float4 a_st[4];
    float4 b_st[2];

    const bool a_valid[4] = {bm + a_row_in + 0 < N_NODES,
                             bm + a_row_in + 32 < N_NODES,
                             bm + a_row_in + 64 < N_NODES,
                             bm + a_row_in + 96 < N_NODES};

    auto ldg_tile = [&](int kt) {
#pragma unroll
        for (int i = 0; i < 4; i++) {
            int gm = bm + a_row_in + i * 32;
            a_st[i] = make_float4(0.f, 0.f, 0.f, 0.f);
            if (a_valid[i])
                a_st[i] = *(const float4*)(X + (size_t)gm * IN_DIM + kt * GBK + a_k4);
        }
#pragma unroll
        for (int i = 0; i < 2; i++) {
            int k = b_k_in + i * 16;
            b_st[i] = *(const float4*)(W + (size_t)(kt * GBK + k) * HD + bn + b_n4);
        }
    };

    auto sts_tile = [&](int buf) {
#pragma unroll
        for (int i = 0; i < 4; i++) {
            int row = a_row_in + i * 32;
            As[buf][row][a_k4 + 0] = f32_to_tf32(a_st[i].x);
            As[buf][row][a_k4 + 1] = f32_to_tf32(a_st[i].y);
            As[buf][row][a_k4 + 2] = f32_to_tf32(a_st[i].z);
            As[buf][row][a_k4 + 3] = f32_to_tf32(a_st[i].w);
        }
#pragma unroll
        for (int i = 0; i < 2; i++) {
            int k = b_k_in + i * 16;
            Bs[buf][k][b_n4 + 0] = f32_to_tf32(b_st[i].x);
            Bs[buf][k][b_n4 + 1] = f32_to_tf32(b_st[i].y);
            Bs[buf][k][b_n4 + 2] = f32_to_tf32(b_st[i].z);
            Bs[buf][k][b_n4 + 3] = f32_to_tf32(b_st[i].w);
        }
    };

    // prologue: tile 0 -> smem[0]; tile 1 -> regs
    ldg_tile(0);
    sts_tile(0);
    ldg_tile(1);
    __syncthreads();

    int buf = 0;
    for (int kt = 0; kt < NKT; kt++) {
        if (kt + 1 < NKT) {
            sts_tile(buf ^ 1);
            if (kt + 2 < NKT) ldg_tile(kt + 2);
        }

#pragma unroll
        for (int kk = 0; kk < GBK; kk += 8) {
            uint32_t af[2][4];
#pragma unroll
            for (int mt = 0; mt < 2; mt++) {
                int rb = warp_m * 32 + mt * 16;
                af[mt][0] = As[buf][rb + lg][kk + lt];
                af[mt][1] = As[buf][rb + lg + 8][kk + lt];
                af[mt][2] = As[buf][rb + lg][kk + lt + 4];
                af[mt][3] = As[buf][rb + lg + 8][kk + lt + 4];
            }
            uint32_t bf[4][2];
#pragma unroll
            for (int nt = 0; nt < 4; nt++) {
                int cb = warp_n * 32 + nt * 8;
                bf[nt][0] = Bs[buf][kk + lt][cb + lg];
                bf[nt][1] = Bs[buf][kk + lt + 4][cb + lg];
            }
#pragma unroll
            for (int mt = 0; mt < 2; mt++)
#pragma unroll
                for (int nt = 0; nt < 4; nt++) {
                    asm volatile(
                        "mma.sync.aligned.m16n8k8.row.col.f32.tf32.tf32.f32 "
                        "{%0,%1,%2,%3}, {%4,%5,%6,%7}, {%8,%9}, {%0,%1,%2,%3};"
                        : "+f"(acc[mt][nt][0]), "+f"(acc[mt][nt][1]),
                          "+f"(acc[mt][nt][2]), "+f"(acc[mt][nt][3])
                        : "r"(af[mt][0]), "r"(af[mt][1]), "r"(af[mt][2]),
                          "r"(af[mt][3]), "r"(bf[nt][0]), "r"(bf[nt][1]));
                }
        }
        __syncthreads();
        buf ^= 1;
    }

#pragma unroll
    for (int mt = 0; mt < 2; mt++) {
#pragma unroll
        for (int nt = 0; nt < 4; nt++) {
            int row0 = bm + warp_m * 32 + mt * 16 + lg;
            int col = bn + warp_n * 32 + nt * 8 + 2 * lt;
            if (row0 < N_NODES) {
                float2 v = make_float2(acc[mt][nt][0], acc[mt][nt][1]);
                *(float2*)&g_h[(size_t)row0 * HD + col] = v;
            }
            int row1 = row0 + 8;
            if (row1 < N_NODES) {
                float2 v = make_float2(acc[mt][nt][2], acc[mt][nt][3]);
                *(float2*)&g_h[(size_t)row1 * HD + col] = v;
            }
        }
    }
}

// ---------------- fp16 copy of h (coalesced) ----------------
__global__ void gat_h16_kernel() {
    int i = blockIdx.x * blockDim.x + threadIdx.x;  // half2 index
    if (i >= N_NODES * HD / 2) return;
    float2 v = ((const float2*)g_h)[i];
    ((__half2*)g_h16)[i] = __floats2half2_rn(v.x, v.y);
}

// ---------------- per-(node,head) attention scores ----------------
__global__ void gat_score_kernel(const float* __restrict__ a) {
    int i = blockIdx.x * blockDim.x + threadIdx.x;
    if (i >= N_NODES * HEADS) return;
    int node = i >> 2;
    int head = i & 3;
    const float* hp = g_h + (size_t)node * HD + head * OUT_DIM;
    const float* asrc = a + head * (2 * OUT_DIM);
    const float* adst = asrc + OUT_DIM;
    float ss = 0.f, sd = 0.f;
#pragma unroll 8
    for (int d = 0; d < OUT_DIM; d++) {
        float hv = hp[d];
        ss += hv * asrc[d];
        sd += hv * adst[d];
    }
    g_ssrc[i] = ss;
    g_sdst[i] = sd;
}

// ---------------- zero counters + sums ----------------
__global__ void gat_zero_kernel() {
    int i = blockIdx.x * blockDim.x + threadIdx.x;
    if (i < N_NODES) g_cnt[i] = 0;
    if (i < N_NODES * HEADS) g_sum[i] = 0.f;
}

// ----- fused edge pass: histogram + leaky_relu + exp + segment sum -------
__global__ void gat_edge_kernel(const int* __restrict__ edges) {
    int e = blockIdx.x * blockDim.x + threadIdx.x;
    if (e >= N_EDGES) return;
    int2 ed = ((const int2*)edges)[e];
    float4 ss = *(const float4*)&g_ssrc[ed.x * HEADS];
    float4 sd = *(const float4*)&g_sdst[ed.y * HEADS];
    float4 v;
    v.x = ss.x + sd.x; v.x = (v.x > 0.f) ? v.x : 0.2f * v.x;
    v.y = ss.y + sd.y; v.y = (v.y > 0.f) ? v.y : 0.2f * v.y;
    v.z = ss.z + sd.z; v.z = (v.z > 0.f) ? v.z : 0.2f * v.z;
    v.w = ss.w + sd.w; v.w = (v.w > 0.f) ? v.w : 0.2f * v.w;
    v.x = __expf(v.x);
    v.y = __expf(v.y);
    v.z = __expf(v.z);
    v.w = __expf(v.w);
    *(float4*)&g_e[e * HEADS] = v;
    float* sp = &g_sum[ed.x * HEADS];
    atomicAdd(sp + 0, v.x);
    atomicAdd(sp + 1, v.y);
    atomicAdd(sp + 2, v.z);
    atomicAdd(sp + 3, v.w);
    atomicAdd(&g_cnt[ed.y], 1);
}

// ---------------- block scan phase 1 ----------------
__global__ void gat_scan1_kernel() {
    __shared__ int s[256];
    int t = threadIdx.x;
    int i = blockIdx.x * 256 + t;
    int v = (i < N_NODES) ? g_cnt[i] : 0;
    s[t] = v;
    __syncthreads();
#pragma unroll
    for (int off = 1; off < 256; off <<= 1) {
        int u = (t >= off) ? s[t - off] : 0;
        __syncthreads();
        s[t] += u;
        __syncthreads();
    }
    if (i < N_NODES) g_offs[i] = s[t] - v;
    if (t == 255) g_part[blockIdx.x] = s[255];
}

// ---------------- scan phase 2 ----------------
__global__ void gat_scan2_kernel(int nblk) {
    __shared__ int s[256];
    int t = threadIdx.x;
    int v = (t < nblk) ? g_part[t] : 0;
    s[t] = v;
    __syncthreads();
#pragma unroll
    for (int off = 1; off < 256; off <<= 1) {
        int u = (t >= off) ? s[t - off] : 0;
        __syncthreads();
        s[t] += u;
        __syncthreads();
    }
    g_part[t] = s[t] - v;
}

// ---------------- scan phase 3 ----------------
__global__ void gat_scan3_kernel() {
    int i = blockIdx.x * blockDim.x + threadIdx.x;
    if (i < N_NODES) {
        g_offs[i] += g_part[i >> 8];
        g_cnt[i] = 0;
    }
    if (i == 0) g_offs[N_NODES] = N_EDGES;
}

// ---------------- reciprocal of denominators ----------------
__global__ void gat_rsum_kernel() {
    int i = blockIdx.x * blockDim.x + threadIdx.x;
    if (i >= N_NODES * HEADS) return;
    g_sum[i] = __frcp_rn(g_sum[i] + 1e-10f);
}

// ---------------- CSR fill ----------------
__global__ void gat_fill_kernel(const int* __restrict__ edges) {
    int e = blockIdx.x * blockDim.x + threadIdx.x;
    if (e >= N_EDGES) return;
    int2 ed = ((const int2*)edges)[e];
    int pos = g_offs[ed.y] + atomicAdd(&g_cnt[ed.y], 1);
    g_csr[pos] = make_int2(ed.x, e);
}

// ---------------- alpha = exp * rsum[src]  (coalesced, in place) --------
__global__ void gat_alpha_kernel(const int* __restrict__ edges) {
    int e = blockIdx.x * blockDim.x + threadIdx.x;
    if (e >= N_EDGES) return;
    int src = edges[2 * e];
    float4 ex = *(const float4*)&g_e[e * HEADS];
    float4 r = *(const float4*)&g_sum[src * HEADS];
    ex.x *= r.x; ex.y *= r.y; ex.z *= r.z; ex.w *= r.w;
    *(float4*)&g_e[e * HEADS] = ex;
}

// ------- aggregation: 64 threads/node, fp16 gather, plain stores -------
__global__ __launch_bounds__(256) void gat_aggregate_kernel(
    float* __restrict__ out, const float* __restrict__ bias) {
    int node = blockIdx.x * 4 + (threadIdx.x >> 6);
    if (node >= N_NODES) return;
    int t = threadIdx.x & 63;     // owns cols [4t, 4t+4)
    int head = t >> 4;

    int beg = g_offs[node];
    int end = g_offs[node + 1];

    float4 acc = make_float4(0.f, 0.f, 0.f, 0.f);
    int i = beg;
    for (; i + 1 < end; i += 2) {
        int2 s0 = g_csr[i];
        int2 s1 = g_csr[i + 1];
        float a0 = g_e[s0.y * HEADS + head];
        float a1 = g_e[s1.y * HEADS + head];
        uint2 p0 = *(const uint2*)&g_h16[(size_t)s0.x * HD + t * 4];
        uint2 p1 = *(const uint2*)&g_h16[(size_t)s1.x * HD + t * 4];
        float2 f00 = __half22float2(*(const __half2*)&p0.x);
        float2 f01 = __half22float2(*(const __half2*)&p0.y);
        float2 f10 = __half22float2(*(const __half2*)&p1.x);
        float2 f11 = __half22float2(*(const __half2*)&p1.y);
        acc.x += a0 * f00.x + a1 * f10.x;
        acc.y += a0 * f00.y + a1 * f10.y;
        acc.z += a0 * f01.x + a1 * f11.x;
        acc.w += a0 * f01.y + a1 * f11.y;
    }
    if (i < end) {
        int2 s0 = g_csr[i];
        float a0 = g_e[s0.y * HEADS + head];
        uint2 p0 = *(const uint2*)&g_h16[(size_t)s0.x * HD + t * 4];
        float2 f00 = __half22float2(*(const __half2*)&p0.x);
        float2 f01 = __half22float2(*(const __half2*)&p0.y);
        acc.x += a0 * f00.x;
        acc.y += a0 * f00.y;
        acc.z += a0 * f01.x;
        acc.w += a0 * f01.y;
    }

    float4 b = *(const float4*)&bias[t * 4];
    acc.x += b.x; acc.y += b.y; acc.z += b.z; acc.w += b.w;
    *(float4*)&out[(size_t)node * HD + t * 4] = acc;
}

// ---------------- launch ----------------
extern "C" void kernel_launch(void* const* d_in, const int* in_sizes, int n_in,
                              void* d_out, int out_size) {
    const float* x     = (const float*)d_in[0];
    const int*   edges = (const int*)d_in[1];
    const float* W     = (const float*)d_in[2];
    const float* a     = (const float*)d_in[3];
    const float* bias  = (const float*)d_in[4];
    float* out = (float*)d_out;

    const int nh = N_NODES * HEADS;
    const int nblk_scan = (N_NODES + 255) / 256;  // 196

    gat_zero_kernel<<<(nh + 255) / 256, 256>>>();

    dim3 gemm_grid((N_NODES + GBM - 1) / GBM, HD / GBN);
    gat_gemm_tf32_kernel<<<gemm_grid, 256>>>(x, W);

    gat_h16_kernel<<<(N_NODES * HD / 2 + 255) / 256, 256>>>();
    gat_score_kernel<<<(nh + 255) / 256, 256>>>(a);
    gat_edge_kernel<<<(N_EDGES + 255) / 256, 256>>>(edges);

    gat_scan1_kernel<<<nblk_scan, 256>>>();
    gat_scan2_kernel<<<1, 256>>>(nblk_scan);
    gat_scan3_kernel<<<nblk_scan, 256>>>();
    gat_rsum_kernel<<<(nh + 255) / 256, 256>>>();
    gat_fill_kernel<<<(N_EDGES + 255) / 256, 256>>>(edges);
    gat_alpha_kernel<<<(N_EDGES + 255) / 256, 256>>>(edges);

    gat_aggregate_kernel<<<(N_NODES + 3) / 4, 256>>>(out, bias);
}

// round 9
// speedup vs baseline: 1.8810x; 1.2647x over previous
#include <cuda_runtime.h>
#include <cuda_fp16.h>
#include <cuda_bf16.h>
#include <cstdint>

#define N_NODES 50000
#define N_EDGES 800000
#define IN_DIM 512
#define HEADS 4
#define OUT_DIM 64
#define HD 256  // HEADS*OUT_DIM

// ---------------- scratch (device globals; no runtime alloc) ----------------
__device__ float  g_h[N_NODES * HD];         // 51.2 MB fp32 features
__device__ __half g_h16[N_NODES * HD];       // 25.6 MB fp16 copy (gather)
__device__ float  g_ssrc[N_NODES * HEADS];
__device__ float  g_sdst[N_NODES * HEADS];
__device__ float  g_e[N_EDGES * HEADS];      // exp values -> alpha (in place)
__device__ float  g_sum[N_NODES * HEADS];    // sum -> reciprocal
__device__ int    g_cnt[N_NODES];
__device__ int    g_offs[N_NODES + 1];
__device__ int    g_part[256];
__device__ int2   g_csr[N_EDGES];            // (src, edge_id) grouped by dst

// ================= TF32 MMA GEMM, double-buffered ==========================
#define GBM 128
#define GBN 64
#define GBK 32
#define NKT (IN_DIM / GBK)   // 16

__device__ __forceinline__ uint32_t f32_to_tf32(float f) {
    uint32_t r;
    asm("cvt.rna.tf32.f32 %0, %1;" : "=r"(r) : "f"(f));
    return r;
}

__global__ __launch_bounds__(256) void gat_gemm_tf32_kernel(
    const float* __restrict__ X, const float* __restrict__ W) {
    __shared__ uint32_t As[2][GBM][GBK + 4];   // [buf][m][k]
    __shared__ uint32_t Bs[2][GBK][GBN + 4];   // [buf][k][n]

    const int tid = threadIdx.x;
    const int lane = tid & 31;
    const int warp = tid >> 5;
    const int warp_m = warp >> 1;
    const int warp_n = warp & 1;

    const int bm = blockIdx.x * GBM;
    const int bn = blockIdx.y * GBN;

    float acc[2][4][4];
#pragma unroll
    for (int i = 0; i < 2; i++)
#pragma unroll
        for (int j = 0; j < 4; j++)
#pragma unroll
            for (int r = 0; r < 4; r++) acc[i][j][r] = 0.f;

    const int a_row_in = tid >> 3;          // 0..31, + i*32
    const int a_k4 = (tid & 7) * 4;
    const int b_k_in = tid >> 4;            // 0..15, + i*16
    const int b_n4 = (tid & 15) * 4;

    const int lg = lane >> 2;
    const int lt = lane & 3;

    float4 a_st[4];
    float4 b_st[2];

    const bool a_valid[4] = {bm + a_row_in + 0 < N_NODES,
                             bm + a_row_in + 32 < N_NODES,
                             bm + a_row_in + 64 < N_NODES,
                             bm + a_row_in + 96 < N_NODES};

    auto ldg_tile = [&](int kt) {
#pragma unroll
        for (int i = 0; i < 4; i++) {
            int gm = bm + a_row_in + i * 32;
            a_st[i] = make_float4(0.f, 0.f, 0.f, 0.f);
            if (a_valid[i])
                a_st[i] = *(const float4*)(X + (size_t)gm * IN_DIM + kt * GBK + a_k4);
        }
#pragma unroll
        for (int i = 0; i < 2; i++) {
            int k = b_k_in + i * 16;
            b_st[i] = *(const float4*)(W + (size_t)(kt * GBK + k) * HD + bn + b_n4);
        }
    };

    auto sts_tile = [&](int buf) {
#pragma unroll
        for (int i = 0; i < 4; i++) {
            int row = a_row_in + i * 32;
            As[buf][row][a_k4 + 0] = f32_to_tf32(a_st[i].x);
            As[buf][row][a_k4 + 1] = f32_to_tf32(a_st[i].y);
            As[buf][row][a_k4 + 2] = f32_to_tf32(a_st[i].z);
            As[buf][row][a_k4 + 3] = f32_to_tf32(a_st[i].w);
        }
#pragma unroll
        for (int i = 0; i < 2; i++) {
            int k = b_k_in + i * 16;
            Bs[buf][k][b_n4 + 0] = f32_to_tf32(b_st[i].x);
            Bs[buf][k][b_n4 + 1] = f32_to_tf32(b_st[i].y);
            Bs[buf][k][b_n4 + 2] = f32_to_tf32(b_st[i].z);
            Bs[buf][k][b_n4 + 3] = f32_to_tf32(b_st[i].w);
        }
    };

    ldg_tile(0);
    sts_tile(0);
    ldg_tile(1);
    __syncthreads();

    int buf = 0;
    for (int kt = 0; kt < NKT; kt++) {
        if (kt + 1 < NKT) {
            sts_tile(buf ^ 1);
            if (kt + 2 < NKT) ldg_tile(kt + 2);
        }

#pragma unroll
        for (int kk = 0; kk < GBK; kk += 8) {
            uint32_t af[2][4];
#pragma unroll
            for (int mt = 0; mt < 2; mt++) {
                int rb = warp_m * 32 + mt * 16;
                af[mt][0] = As[buf][rb + lg][kk + lt];
                af[mt][1] = As[buf][rb + lg + 8][kk + lt];
                af[mt][2] = As[buf][rb + lg][kk + lt + 4];
                af[mt][3] = As[buf][rb + lg + 8][kk + lt + 4];
            }
            uint32_t bf[4][2];
#pragma unroll
            for (int nt = 0; nt < 4; nt++) {
                int cb = warp_n * 32 + nt * 8;
                bf[nt][0] = Bs[buf][kk + lt][cb + lg];
                bf[nt][1] = Bs[buf][kk + lt + 4][cb + lg];
            }
#pragma unroll
            for (int mt = 0; mt < 2; mt++)
#pragma unroll
                for (int nt = 0; nt < 4; nt++) {
                    asm volatile(
                        "mma.sync.aligned.m16n8k8.row.col.f32.tf32.tf32.f32 "
                        "{%0,%1,%2,%3}, {%4,%5,%6,%7}, {%8,%9}, {%0,%1,%2,%3};"
                        : "+f"(acc[mt][nt][0]), "+f"(acc[mt][nt][1]),
                          "+f"(acc[mt][nt][2]), "+f"(acc[mt][nt][3])
                        : "r"(af[mt][0]), "r"(af[mt][1]), "r"(af[mt][2]),
                          "r"(af[mt][3]), "r"(bf[nt][0]), "r"(bf[nt][1]));
                }
        }
        __syncthreads();
        buf ^= 1;
    }

#pragma unroll
    for (int mt = 0; mt < 2; mt++) {
#pragma unroll
        for (int nt = 0; nt < 4; nt++) {
            int row0 = bm + warp_m * 32 + mt * 16 + lg;
            int col = bn + warp_n * 32 + nt * 8 + 2 * lt;
            if (row0 < N_NODES) {
                float2 v = make_float2(acc[mt][nt][0], acc[mt][nt][1]);
                *(float2*)&g_h[(size_t)row0 * HD + col] = v;
            }
            int row1 = row0 + 8;
            if (row1 < N_NODES) {
                float2 v = make_float2(acc[mt][nt][2], acc[mt][nt][3]);
                *(float2*)&g_h[(size_t)row1 * HD + col] = v;
            }
        }
    }
}

// ------- fused: fp16 convert + per-(node,head) scores (coalesced) --------
// 64 threads per node; thread t owns cols [4t, 4t+4); head = t>>4.
// 16-lane segmented reduction gives one (node, head) score pair.
__global__ __launch_bounds__(256) void gat_h16score_kernel(
    const float* __restrict__ a) {
    int node = blockIdx.x * 4 + (threadIdx.x >> 6);
    if (node >= N_NODES) return;
    int t = threadIdx.x & 63;
    int head = t >> 4;
    int cih = (t & 15) * 4;   // col within head

    // coalesced load of this node's 4 cols
    float4 v = *(const float4*)&g_h[(size_t)node * HD + t * 4];

    // fp16 convert (coalesced 8B store)
    __half2 h01 = __floats2half2_rn(v.x, v.y);
    __half2 h23 = __floats2half2_rn(v.z, v.w);
    uint2 packed;
    packed.x = *(const uint32_t*)&h01;
    packed.y = *(const uint32_t*)&h23;
    *(uint2*)&g_h16[(size_t)node * HD + t * 4] = packed;

    // partial dots with a_src / a_dst  (a is [HEADS][2*OUT_DIM])
    const float* ah = a + head * (2 * OUT_DIM);
    float4 as = *(const float4*)&ah[cih];
    float4 ad = *(const float4*)&ah[OUT_DIM + cih];
    float ss = v.x * as.x + v.y * as.y + v.z * as.z + v.w * as.w;
    float sd = v.x * ad.x + v.y * ad.y + v.z * ad.z + v.w * ad.w;

    // 16-lane segmented reduction (segments align with heads)
#pragma unroll
    for (int off = 8; off >= 1; off >>= 1) {
        ss += __shfl_xor_sync(0xffffffffu, ss, off, 16);
        sd += __shfl_xor_sync(0xffffffffu, sd, off, 16);
    }
    if ((t & 15) == 0) {
        g_ssrc[node * HEADS + head] = ss;
        g_sdst[node * HEADS + head] = sd;
    }
}

// ---------------- zero counters + sums ----------------
__global__ void gat_zero_kernel() {
    int i = blockIdx.x * blockDim.x + threadIdx.x;
    if (i < N_NODES) g_cnt[i] = 0;
    if (i < N_NODES * HEADS) g_sum[i] = 0.f;
}

// ----- fused edge pass: histogram + leaky_relu + exp + segment sum -------
__global__ void gat_edge_kernel(const int* __restrict__ edges) {
    int e = blockIdx.x * blockDim.x + threadIdx.x;
    if (e >= N_EDGES) return;
    int2 ed = ((const int2*)edges)[e];
    float4 ss = *(const float4*)&g_ssrc[ed.x * HEADS];
    float4 sd = *(const float4*)&g_sdst[ed.y * HEADS];
    float4 v;
    v.x = ss.x + sd.x; v.x = (v.x > 0.f) ? v.x : 0.2f * v.x;
    v.y = ss.y + sd.y; v.y = (v.y > 0.f) ? v.y : 0.2f * v.y;
    v.z = ss.z + sd.z; v.z = (v.z > 0.f) ? v.z : 0.2f * v.z;
    v.w = ss.w + sd.w; v.w = (v.w > 0.f) ? v.w : 0.2f * v.w;
    v.x = __expf(v.x);
    v.y = __expf(v.y);
    v.z = __expf(v.z);
    v.w = __expf(v.w);
    *(float4*)&g_e[e * HEADS] = v;
    float* sp = &g_sum[ed.x * HEADS];
    atomicAdd(sp + 0, v.x);
    atomicAdd(sp + 1, v.y);
    atomicAdd(sp + 2, v.z);
    atomicAdd(sp + 3, v.w);
    atomicAdd(&g_cnt[ed.y], 1);
}

// ---------------- block scan phase 1 ----------------
__global__ void gat_scan1_kernel() {
    __shared__ int s[256];
    int t = threadIdx.x;
    int i = blockIdx.x * 256 + t;
    int v = (i < N_NODES) ? g_cnt[i] : 0;
    s[t] = v;
    __syncthreads();
#pragma unroll
    for (int off = 1; off < 256; off <<= 1) {
        int u = (t >= off) ? s[t - off] : 0;
        __syncthreads();
        s[t] += u;
        __syncthreads();
    }
    if (i < N_NODES) g_offs[i] = s[t] - v;
    if (t == 255) g_part[blockIdx.x] = s[255];
}

// ---------------- scan phase 2 ----------------
__global__ void gat_scan2_kernel(int nblk) {
    __shared__ int s[256];
    int t = threadIdx.x;
    int v = (t < nblk) ? g_part[t] : 0;
    s[t] = v;
    __syncthreads();
#pragma unroll
    for (int off = 1; off < 256; off <<= 1) {
        int u = (t >= off) ? s[t - off] : 0;
        __syncthreads();
        s[t] += u;
        __syncthreads();
    }
    g_part[t] = s[t] - v;
}

// ---------------- scan phase 3 ----------------
__global__ void gat_scan3_kernel() {
    int i = blockIdx.x * blockDim.x + threadIdx.x;
    if (i < N_NODES) {
        g_offs[i] += g_part[i >> 8];
        g_cnt[i] = 0;
    }
    if (i == 0) g_offs[N_NODES] = N_EDGES;
}

// ---------------- reciprocal of denominators ----------------
__global__ void gat_rsum_kernel() {
    int i = blockIdx.x * blockDim.x + threadIdx.x;
    if (i >= N_NODES * HEADS) return;
    g_sum[i] = __frcp_rn(g_sum[i] + 1e-10f);
}

// ---------------- CSR fill ----------------
__global__ void gat_fill_kernel(const int* __restrict__ edges) {
    int e = blockIdx.x * blockDim.x + threadIdx.x;
    if (e >= N_EDGES) return;
    int2 ed = ((const int2*)edges)[e];
    int pos = g_offs[ed.y] + atomicAdd(&g_cnt[ed.y], 1);
    g_csr[pos] = make_int2(ed.x, e);
}

// ---------------- alpha = exp * rsum[src]  (coalesced, in place) --------
__global__ void gat_alpha_kernel(const int* __restrict__ edges) {
    int e = blockIdx.x * blockDim.x + threadIdx.x;
    if (e >= N_EDGES) return;
    int src = edges[2 * e];
    float4 ex = *(const float4*)&g_e[e * HEADS];
    float4 r = *(const float4*)&g_sum[src * HEADS];
    ex.x *= r.x; ex.y *= r.y; ex.z *= r.z; ex.w *= r.w;
    *(float4*)&g_e[e * HEADS] = ex;
}

// ------- aggregation: 64 threads/node, fp16 gather, plain stores -------
__global__ __launch_bounds__(256) void gat_aggregate_kernel(
    float* __restrict__ out, const float* __restrict__ bias) {
    int node = blockIdx.x * 4 + (threadIdx.x >> 6);
    if (node >= N_NODES) return;
    int t = threadIdx.x & 63;     // owns cols [4t, 4t+4)
    int head = t >> 4;

    int beg = g_offs[node];
    int end = g_offs[node + 1];

    float4 acc = make_float4(0.f, 0.f, 0.f, 0.f);
    int i = beg;
    for (; i + 1 < end; i += 2) {
        int2 s0 = g_csr[i];
        int2 s1 = g_csr[i + 1];
        float a0 = g_e[s0.y * HEADS + head];
        float a1 = g_e[s1.y * HEADS + head];
        uint2 p0 = *(const uint2*)&g_h16[(size_t)s0.x * HD + t * 4];
        uint2 p1 = *(const uint2*)&g_h16[(size_t)s1.x * HD + t * 4];
        float2 f00 = __half22float2(*(const __half2*)&p0.x);
        float2 f01 = __half22float2(*(const __half2*)&p0.y);
        float2 f10 = __half22float2(*(const __half2*)&p1.x);
        float2 f11 = __half22float2(*(const __half2*)&p1.y);
        acc.x += a0 * f00.x + a1 * f10.x;
        acc.y += a0 * f00.y + a1 * f10.y;
        acc.z += a0 * f01.x + a1 * f11.x;
        acc.w += a0 * f01.y + a1 * f11.y;
    }
    if (i < end) {
        int2 s0 = g_csr[i];
        float a0 = g_e[s0.y * HEADS + head];
        uint2 p0 = *(const uint2*)&g_h16[(size_t)s0.x * HD + t * 4];
        float2 f00 = __half22float2(*(const __half2*)&p0.x);
        float2 f01 = __half22float2(*(const __half2*)&p0.y);
        acc.x += a0 * f00.x;
        acc.y += a0 * f00.y;
        acc.z += a0 * f01.x;
        acc.w += a0 * f01.y;
    }

    float4 b = *(const float4*)&bias[t * 4];
    acc.x += b.x; acc.y += b.y; acc.z += b.z; acc.w += b.w;
    *(float4*)&out[(size_t)node * HD + t * 4] = acc;
}

// ---------------- launch ----------------
extern "C" void kernel_launch(void* const* d_in, const int* in_sizes, int n_in,
                              void* d_out, int out_size) {
    const float* x     = (const float*)d_in[0];
    const int*   edges = (const int*)d_in[1];
    const float* W     = (const float*)d_in[2];
    const float* a     = (const float*)d_in[3];
    const float* bias  = (const float*)d_in[4];
    float* out = (float*)d_out;

    const int nh = N_NODES * HEADS;
    const int nblk_scan = (N_NODES + 255) / 256;  // 196

    gat_zero_kernel<<<(nh + 255) / 256, 256>>>();

    dim3 gemm_grid((N_NODES + GBM - 1) / GBM, HD / GBN);
    gat_gemm_tf32_kernel<<<gemm_grid, 256>>>(x, W);

    gat_h16score_kernel<<<(N_NODES + 3) / 4, 256>>>(a);
    gat_edge_kernel<<<(N_EDGES + 255) / 256, 256>>>(edges);

    gat_scan1_kernel<<<nblk_scan, 256>>>();
    gat_scan2_kernel<<<1, 256>>>(nblk_scan);
    gat_scan3_kernel<<<nblk_scan, 256>>>();
    gat_rsum_kernel<<<(nh + 255) / 256, 256>>>();
    gat_fill_kernel<<<(N_EDGES + 255) / 256, 256>>>(edges);
    gat_alpha_kernel<<<(N_EDGES + 255) / 256, 256>>>(edges);

    gat_aggregate_kernel<<<(N_NODES + 3) / 4, 256>>>(out, bias);
}

// round 10
// speedup vs baseline: 1.9007x; 1.0105x over previous
#include <cuda_runtime.h>
#include <cuda_fp16.h>
#include <cuda_bf16.h>
#include <cstdint>

#define N_NODES 50000
#define N_EDGES 800000
#define IN_DIM 512
#define HEADS 4
#define OUT_DIM 64
#define HD 256  // HEADS*OUT_DIM

// ---------------- scratch (device globals; no runtime alloc) ----------------
__device__ float  g_h[N_NODES * HD];         // 51.2 MB fp32 features
__device__ __half g_h16[N_NODES * HD];       // 25.6 MB fp16 copy (gather)
__device__ float  g_ssrc[N_NODES * HEADS];
__device__ float  g_sdst[N_NODES * HEADS];
__device__ float  g_e[N_EDGES * HEADS];      // exp values (edge order)
__device__ float  g_sum[N_NODES * HEADS];    // sum -> reciprocal
__device__ int    g_cnt[N_NODES];
__device__ int    g_offs[N_NODES + 1];
__device__ int    g_part[256];
__device__ int2   g_csr[N_EDGES];            // (src, edge_id) grouped by dst

// ================= TF32 MMA GEMM, double-buffered ==========================
#define GBM 128
#define GBN 64
#define GBK 32
#define NKT (IN_DIM / GBK)   // 16

__device__ __forceinline__ uint32_t f32_to_tf32(float f) {
    uint32_t r;
    asm("cvt.rna.tf32.f32 %0, %1;" : "=r"(r) : "f"(f));
    return r;
}

__global__ __launch_bounds__(256) void gat_gemm_tf32_kernel(
    const float* __restrict__ X, const float* __restrict__ W) {
    __shared__ uint32_t As[2][GBM][GBK + 4];   // [buf][m][k]
    __shared__ uint32_t Bs[2][GBK][GBN + 4];   // [buf][k][n]

    const int tid = threadIdx.x;
    const int lane = tid & 31;
    const int warp = tid >> 5;
    const int warp_m = warp >> 1;
    const int warp_n = warp & 1;

    const int bm = blockIdx.x * GBM;
    const int bn = blockIdx.y * GBN;

    float acc[2][4][4];
#pragma unroll
    for (int i = 0; i < 2; i++)
#pragma unroll
        for (int j = 0; j < 4; j++)
#pragma unroll
            for (int r = 0; r < 4; r++) acc[i][j][r] = 0.f;

    const int a_row_in = tid >> 3;          // 0..31, + i*32
    const int a_k4 = (tid & 7) * 4;
    const int b_k_in = tid >> 4;            // 0..15, + i*16
    const int b_n4 = (tid & 15) * 4;

    const int lg = lane >> 2;
    const int lt = lane & 3;

    float4 a_st[4];
    float4 b_st[2];

    const bool a_valid[4] = {bm + a_row_in + 0 < N_NODES,
                             bm + a_row_in + 32 < N_NODES,
                             bm + a_row_in + 64 < N_NODES,
                             bm + a_row_in + 96 < N_NODES};

    auto ldg_tile = [&](int kt) {
#pragma unroll
        for (int i = 0; i < 4; i++) {
            int gm = bm + a_row_in + i * 32;
            a_st[i] = make_float4(0.f, 0.f, 0.f, 0.f);
            if (a_valid[i])
                a_st[i] = *(const float4*)(X + (size_t)gm * IN_DIM + kt * GBK + a_k4);
        }
#pragma unroll
        for (int i = 0; i < 2; i++) {
            int k = b_k_in + i * 16;
            b_st[i] = *(const float4*)(W + (size_t)(kt * GBK + k) * HD + bn + b_n4);
        }
    };

    auto sts_tile = [&](int buf) {
#pragma unroll
        for (int i = 0; i < 4; i++) {
            int row = a_row_in + i * 32;
            As[buf][row][a_k4 + 0] = f32_to_tf32(a_st[i].x);
            As[buf][row][a_k4 + 1] = f32_to_tf32(a_st[i].y);
            As[buf][row][a_k4 + 2] = f32_to_tf32(a_st[i].z);
            As[buf][row][a_k4 + 3] = f32_to_tf32(a_st[i].w);
        }
#pragma unroll
        for (int i = 0; i < 2; i++) {
            int k = b_k_in + i * 16;
            Bs[buf][k][b_n4 + 0] = f32_to_tf32(b_st[i].x);
            Bs[buf][k][b_n4 + 1] = f32_to_tf32(b_st[i].y);
            Bs[buf][k][b_n4 + 2] = f32_to_tf32(b_st[i].z);
            Bs[buf][k][b_n4 + 3] = f32_to_tf32(b_st[i].w);
        }
    };

    ldg_tile(0);
    sts_tile(0);
    ldg_tile(1);
    __syncthreads();

    int buf = 0;
    for (int kt = 0; kt < NKT; kt++) {
        if (kt + 1 < NKT) {
            sts_tile(buf ^ 1);
            if (kt + 2 < NKT) ldg_tile(kt + 2);
        }

#pragma unroll
        for (int kk = 0; kk < GBK; kk += 8) {
            uint32_t af[2][4];
#pragma unroll
            for (int mt = 0; mt < 2; mt++) {
                int rb = warp_m * 32 + mt * 16;
                af[mt][0] = As[buf][rb + lg][kk + lt];
                af[mt][1] = As[buf][rb + lg + 8][kk + lt];
                af[mt][2] = As[buf][rb + lg][kk + lt + 4];
                af[mt][3] = As[buf][rb + lg + 8][kk + lt + 4];
            }
            uint32_t bf[4][2];
#pragma unroll
            for (int nt = 0; nt < 4; nt++) {
                int cb = warp_n * 32 + nt * 8;
                bf[nt][0] = Bs[buf][kk + lt][cb + lg];
                bf[nt][1] = Bs[buf][kk + lt + 4][cb + lg];
            }
#pragma unroll
            for (int mt = 0; mt < 2; mt++)
#pragma unroll
                for (int nt = 0; nt < 4; nt++) {
                    asm volatile(
                        "mma.sync.aligned.m16n8k8.row.col.f32.tf32.tf32.f32 "
                        "{%0,%1,%2,%3}, {%4,%5,%6,%7}, {%8,%9}, {%0,%1,%2,%3};"
                        : "+f"(acc[mt][nt][0]), "+f"(acc[mt][nt][1]),
                          "+f"(acc[mt][nt][2]), "+f"(acc[mt][nt][3])
                        : "r"(af[mt][0]), "r"(af[mt][1]), "r"(af[mt][2]),
                          "r"(af[mt][3]), "r"(bf[nt][0]), "r"(bf[nt][1]));
                }
        }
        __syncthreads();
        buf ^= 1;
    }

#pragma unroll
    for (int mt = 0; mt < 2; mt++) {
#pragma unroll
        for (int nt = 0; nt < 4; nt++) {
            int row0 = bm + warp_m * 32 + mt * 16 + lg;
            int col = bn + warp_n * 32 + nt * 8 + 2 * lt;
            if (row0 < N_NODES) {
                float2 v = make_float2(acc[mt][nt][0], acc[mt][nt][1]);
                *(float2*)&g_h[(size_t)row0 * HD + col] = v;
            }
            int row1 = row0 + 8;
            if (row1 < N_NODES) {
                float2 v = make_float2(acc[mt][nt][2], acc[mt][nt][3]);
                *(float2*)&g_h[(size_t)row1 * HD + col] = v;
            }
        }
    }
}

// ------- fused: fp16 convert + per-(node,head) scores (coalesced) --------
__global__ __launch_bounds__(256) void gat_h16score_kernel(
    const float* __restrict__ a) {
    int node = blockIdx.x * 4 + (threadIdx.x >> 6);
    if (node >= N_NODES) return;
    int t = threadIdx.x & 63;
    int head = t >> 4;
    int cih = (t & 15) * 4;   // col within head

    float4 v = *(const float4*)&g_h[(size_t)node * HD + t * 4];

    __half2 h01 = __floats2half2_rn(v.x, v.y);
    __half2 h23 = __floats2half2_rn(v.z, v.w);
    uint2 packed;
    packed.x = *(const uint32_t*)&h01;
    packed.y = *(const uint32_t*)&h23;
    *(uint2*)&g_h16[(size_t)node * HD + t * 4] = packed;

    const float* ah = a + head * (2 * OUT_DIM);
    float4 as = *(const float4*)&ah[cih];
    float4 ad = *(const float4*)&ah[OUT_DIM + cih];
    float ss = v.x * as.x + v.y * as.y + v.z * as.z + v.w * as.w;
    float sd = v.x * ad.x + v.y * ad.y + v.z * ad.z + v.w * ad.w;

#pragma unroll
    for (int off = 8; off >= 1; off >>= 1) {
        ss += __shfl_xor_sync(0xffffffffu, ss, off, 16);
        sd += __shfl_xor_sync(0xffffffffu, sd, off, 16);
    }
    if ((t & 15) == 0) {
        g_ssrc[node * HEADS + head] = ss;
        g_sdst[node * HEADS + head] = sd;
    }
}

// ---------------- zero counters + sums ----------------
__global__ void gat_zero_kernel() {
    int i = blockIdx.x * blockDim.x + threadIdx.x;
    if (i < N_NODES) g_cnt[i] = 0;
    if (i < N_NODES * HEADS) g_sum[i] = 0.f;
}

// ----- fused edge pass: histogram + leaky_relu + exp + segment sum -------
__global__ void gat_edge_kernel(const int* __restrict__ edges) {
    int e = blockIdx.x * blockDim.x + threadIdx.x;
    if (e >= N_EDGES) return;
    int2 ed = ((const int2*)edges)[e];
    float4 ss = *(const float4*)&g_ssrc[ed.x * HEADS];
    float4 sd = *(const float4*)&g_sdst[ed.y * HEADS];
    float4 v;
    v.x = ss.x + sd.x; v.x = (v.x > 0.f) ? v.x : 0.2f * v.x;
    v.y = ss.y + sd.y; v.y = (v.y > 0.f) ? v.y : 0.2f * v.y;
    v.z = ss.z + sd.z; v.z = (v.z > 0.f) ? v.z : 0.2f * v.z;
    v.w = ss.w + sd.w; v.w = (v.w > 0.f) ? v.w : 0.2f * v.w;
    v.x = __expf(v.x);
    v.y = __expf(v.y);
    v.z = __expf(v.z);
    v.w = __expf(v.w);
    *(float4*)&g_e[e * HEADS] = v;
    float* sp = &g_sum[ed.x * HEADS];
    atomicAdd(sp + 0, v.x);
    atomicAdd(sp + 1, v.y);
    atomicAdd(sp + 2, v.z);
    atomicAdd(sp + 3, v.w);
    atomicAdd(&g_cnt[ed.y], 1);
}

// ---------------- block scan phase 1 ----------------
__global__ void gat_scan1_kernel() {
    __shared__ int s[256];
    int t = threadIdx.x;
    int i = blockIdx.x * 256 + t;
    int v = (i < N_NODES) ? g_cnt[i] : 0;
    s[t] = v;
    __syncthreads();
#pragma unroll
    for (int off = 1; off < 256; off <<= 1) {
        int u = (t >= off) ? s[t - off] : 0;
        __syncthreads();
        s[t] += u;
        __syncthreads();
    }
    if (i < N_NODES) g_offs[i] = s[t] - v;
    if (t == 255) g_part[blockIdx.x] = s[255];
}

// ---------------- scan phase 2 ----------------
__global__ void gat_scan2_kernel(int nblk) {
    __shared__ int s[256];
    int t = threadIdx.x;
    int v = (t < nblk) ? g_part[t] : 0;
    s[t] = v;
    __syncthreads();
#pragma unroll
    for (int off = 1; off < 256; off <<= 1) {
        int u = (t >= off) ? s[t - off] : 0;
        __syncthreads();
        s[t] += u;
        __syncthreads();
    }
    g_part[t] = s[t] - v;
}

// -------- scan phase 3 + reciprocal of denominators (merged) ----------
__global__ void gat_scan3_rsum_kernel() {
    int i = blockIdx.x * blockDim.x + threadIdx.x;
    if (i < N_NODES) {
        g_offs[i] += g_part[i >> 8];
        g_cnt[i] = 0;
    }
    if (i == 0) g_offs[N_NODES] = N_EDGES;
    if (i < N_NODES * HEADS) g_sum[i] = __frcp_rn(g_sum[i] + 1e-10f);
}

// ---------------- CSR fill ----------------
__global__ void gat_fill_kernel(const int* __restrict__ edges) {
    int e = blockIdx.x * blockDim.x + threadIdx.x;
    if (e >= N_EDGES) return;
    int2 ed = ((const int2*)edges)[e];
    int pos = g_offs[ed.y] + atomicAdd(&g_cnt[ed.y], 1);
    g_csr[pos] = make_int2(ed.x, e);
}

// ------- aggregation: 64 threads/node, fp16 gather, alpha inline --------
__global__ __launch_bounds__(256) void gat_aggregate_kernel(
    float* __restrict__ out, const float* __restrict__ bias) {
    int node = blockIdx.x * 4 + (threadIdx.x >> 6);
    if (node >= N_NODES) return;
    int t = threadIdx.x & 63;     // owns cols [4t, 4t+4)
    int head = t >> 4;

    int beg = g_offs[node];
    int end = g_offs[node + 1];

    float4 acc = make_float4(0.f, 0.f, 0.f, 0.f);
    int i = beg;
    for (; i + 3 < end; i += 4) {
        int2 s0 = g_csr[i];
        int2 s1 = g_csr[i + 1];
        int2 s2 = g_csr[i + 2];
        int2 s3 = g_csr[i + 3];
        float a0 = g_e[s0.y * HEADS + head] * g_sum[s0.x * HEADS + head];
        float a1 = g_e[s1.y * HEADS + head] * g_sum[s1.x * HEADS + head];
        float a2 = g_e[s2.y * HEADS + head] * g_sum[s2.x * HEADS + head];
        float a3 = g_e[s3.y * HEADS + head] * g_sum[s3.x * HEADS + head];
        uint2 p0 = *(const uint2*)&g_h16[(size_t)s0.x * HD + t * 4];
        uint2 p1 = *(const uint2*)&g_h16[(size_t)s1.x * HD + t * 4];
        uint2 p2 = *(const uint2*)&g_h16[(size_t)s2.x * HD + t * 4];
        uint2 p3 = *(const uint2*)&g_h16[(size_t)s3.x * HD + t * 4];
        float2 f00 = __half22float2(*(const __half2*)&p0.x);
        float2 f01 = __half22float2(*(const __half2*)&p0.y);
        float2 f10 = __half22float2(*(const __half2*)&p1.x);
        float2 f11 = __half22float2(*(const __half2*)&p1.y);
        float2 f20 = __half22float2(*(const __half2*)&p2.x);
        float2 f21 = __half22float2(*(const __half2*)&p2.y);
        float2 f30 = __half22float2(*(const __half2*)&p3.x);
        float2 f31 = __half22float2(*(const __half2*)&p3.y);
        acc.x += a0 * f00.x + a1 * f10.x + a2 * f20.x + a3 * f30.x;
        acc.y += a0 * f00.y + a1 * f10.y + a2 * f20.y + a3 * f30.y;
        acc.z += a0 * f01.x + a1 * f11.x + a2 * f21.x + a3 * f31.x;
        acc.w += a0 * f01.y + a1 * f11.y + a2 * f21.y + a3 * f31.y;
    }
    for (; i < end; i++) {
        int2 s0 = g_csr[i];
        float a0 = g_e[s0.y * HEADS + head] * g_sum[s0.x * HEADS + head];
        uint2 p0 = *(const uint2*)&g_h16[(size_t)s0.x * HD + t * 4];
        float2 f00 = __half22float2(*(const __half2*)&p0.x);
        float2 f01 = __half22float2(*(const __half2*)&p0.y);
        acc.x += a0 * f00.x;
        acc.y += a0 * f00.y;
        acc.z += a0 * f01.x;
        acc.w += a0 * f01.y;
    }

    float4 b = *(const float4*)&bias[t * 4];
    acc.x += b.x; acc.y += b.y; acc.z += b.z; acc.w += b.w;
    *(float4*)&out[(size_t)node * HD + t * 4] = acc;
}

// ---------------- launch ----------------
extern "C" void kernel_launch(void* const* d_in, const int* in_sizes, int n_in,
                              void* d_out, int out_size) {
    const float* x     = (const float*)d_in[0];
    const int*   edges = (const int*)d_in[1];
    const float* W     = (const float*)d_in[2];
    const float* a     = (const float*)d_in[3];
    const float* bias  = (const float*)d_in[4];
    float* out = (float*)d_out;

    const int nh = N_NODES * HEADS;
    const int nblk_scan = (N_NODES + 255) / 256;  // 196

    gat_zero_kernel<<<(nh + 255) / 256, 256>>>();

    dim3 gemm_grid((N_NODES + GBM - 1) / GBM, HD / GBN);
    gat_gemm_tf32_kernel<<<gemm_grid, 256>>>(x, W);

    gat_h16score_kernel<<<(N_NODES + 3) / 4, 256>>>(a);
    gat_edge_kernel<<<(N_EDGES + 255) / 256, 256>>>(edges);

    gat_scan1_kernel<<<nblk_scan, 256>>>();
    gat_scan2_kernel<<<1, 256>>>(nblk_scan);
    gat_scan3_rsum_kernel<<<(nh + 255) / 256, 256>>>();
    gat_fill_kernel<<<(N_EDGES + 255) / 256, 256>>>(edges);

    gat_aggregate_kernel<<<(N_NODES + 3) / 4, 256>>>(out, bias);
}

// round 15
// speedup vs baseline: 2.0413x; 1.0740x over previous
#include <cuda_runtime.h>
#include <cuda_fp16.h>
#include <cuda_bf16.h>
#include <cstdint>

#define N_NODES 50000
#define N_EDGES 800000
#define IN_DIM 512
#define HEADS 4
#define OUT_DIM 64
#define HD 256  // HEADS*OUT_DIM

// ---------------- scratch (device globals; no runtime alloc) ----------------
__device__ float  g_h[N_NODES * HD];         // 51.2 MB fp32 features
__device__ __half g_h16[N_NODES * HD];       // 25.6 MB fp16 copy (gather)
__device__ float  g_ssrc[N_NODES * HEADS];
__device__ float  g_sdst[N_NODES * HEADS];
__device__ float  g_e[N_EDGES * HEADS];      // exp values (edge order)
__device__ float  g_sum[N_NODES * HEADS];    // sum -> reciprocal
__device__ int    g_cnt[N_NODES];
__device__ int    g_offs[N_NODES + 1];
__device__ int    g_part[256];
__device__ int4   g_csr4[N_EDGES];           // {src, alpha01(h2), alpha23(h2), 0}

// ================= TF32 MMA GEMM, double-buffered ==========================
#define GBM 128
#define GBN 64
#define GBK 32
#define NKT (IN_DIM / GBK)   // 16

__device__ __forceinline__ uint32_t f32_to_tf32(float f) {
    uint32_t r;
    asm("cvt.rna.tf32.f32 %0, %1;" : "=r"(r) : "f"(f));
    return r;
}

__global__ __launch_bounds__(256) void gat_gemm_tf32_kernel(
    const float* __restrict__ X, const float* __restrict__ W) {
    __shared__ uint32_t As[2][GBM][GBK + 4];   // [buf][m][k]
    __shared__ uint32_t Bs[2][GBK][GBN + 4];   // [buf][k][n]

    const int tid = threadIdx.x;
    const int lane = tid & 31;
    const int warp = tid >> 5;
    const int warp_m = warp >> 1;
    const int warp_n = warp & 1;

    const int bm = blockIdx.x * GBM;
    const int bn = blockIdx.y * GBN;

    float acc[2][4][4];
#pragma unroll
    for (int i = 0; i < 2; i++)
#pragma unroll
        for (int j = 0; j < 4; j++)
#pragma unroll
            for (int r = 0; r < 4; r++) acc[i][j][r] = 0.f;

    const int a_row_in = tid >> 3;          // 0..31, + i*32
    const int a_k4 = (tid & 7) * 4;
    const int b_k_in = tid >> 4;            // 0..15, + i*16
    const int b_n4 = (tid & 15) * 4;

    const int lg = lane >> 2;
    const int lt = lane & 3;

    float4 a_st[4];
    float4 b_st[2];

    const bool a_valid[4] = {bm + a_row_in + 0 < N_NODES,
                             bm + a_row_in + 32 < N_NODES,
                             bm + a_row_in + 64 < N_NODES,
                             bm + a_row_in + 96 < N_NODES};

    auto ldg_tile = [&](int kt) {
#pragma unroll
        for (int i = 0; i < 4; i++) {
            int gm = bm + a_row_in + i * 32;
            a_st[i] = make_float4(0.f, 0.f, 0.f, 0.f);
            if (a_valid[i])
                a_st[i] = *(const float4*)(X + (size_t)gm * IN_DIM + kt * GBK + a_k4);
        }
#pragma unroll
        for (int i = 0; i < 2; i++) {
            int k = b_k_in + i * 16;
            b_st[i] = *(const float4*)(W + (size_t)(kt * GBK + k) * HD + bn + b_n4);
        }
    };

    auto sts_tile = [&](int buf) {
#pragma unroll
        for (int i = 0; i < 4; i++) {
            int row = a_row_in + i * 32;
            As[buf][row][a_k4 + 0] = f32_to_tf32(a_st[i].x);
            As[buf][row][a_k4 + 1] = f32_to_tf32(a_st[i].y);
            As[buf][row][a_k4 + 2] = f32_to_tf32(a_st[i].z);
            As[buf][row][a_k4 + 3] = f32_to_tf32(a_st[i].w);
        }
#pragma unroll
        for (int i = 0; i < 2; i++) {
            int k = b_k_in + i * 16;
            Bs[buf][k][b_n4 + 0] = f32_to_tf32(b_st[i].x);
            Bs[buf][k][b_n4 + 1] = f32_to_tf32(b_st[i].y);
            Bs[buf][k][b_n4 + 2] = f32_to_tf32(b_st[i].z);
            Bs[buf][k][b_n4 + 3] = f32_to_tf32(b_st[i].w);
        }
    };

    ldg_tile(0);
    sts_tile(0);
    ldg_tile(1);
    __syncthreads();

    int buf = 0;
    for (int kt = 0; kt < NKT; kt++) {
        if (kt + 1 < NKT) {
            sts_tile(buf ^ 1);
            if (kt + 2 < NKT) ldg_tile(kt + 2);
        }

#pragma unroll
        for (int kk = 0; kk < GBK; kk += 8) {
            uint32_t af[2][4];
#pragma unroll
            for (int mt = 0; mt < 2; mt++) {
                int rb = warp_m * 32 + mt * 16;
                af[mt][0] = As[buf][rb + lg][kk + lt];
                af[mt][1] = As[buf][rb + lg + 8][kk + lt];
                af[mt][2] = As[buf][rb + lg][kk + lt + 4];
                af[mt][3] = As[buf][rb + lg + 8][kk + lt + 4];
            }
            uint32_t bf[4][2];
#pragma unroll
            for (int nt = 0; nt < 4; nt++) {
                int cb = warp_n * 32 + nt * 8;
                bf[nt][0] = Bs[buf][kk + lt][cb + lg];
                bf[nt][1] = Bs[buf][kk + lt + 4][cb + lg];
            }
#pragma unroll
            for (int mt = 0; mt < 2; mt++)
#pragma unroll
                for (int nt = 0; nt < 4; nt++) {
                    asm volatile(
                        "mma.sync.aligned.m16n8k8.row.col.f32.tf32.tf32.f32 "
                        "{%0,%1,%2,%3}, {%4,%5,%6,%7}, {%8,%9}, {%0,%1,%2,%3};"
                        : "+f"(acc[mt][nt][0]), "+f"(acc[mt][nt][1]),
                          "+f"(acc[mt][nt][2]), "+f"(acc[mt][nt][3])
                        : "r"(af[mt][0]), "r"(af[mt][1]), "r"(af[mt][2]),
                          "r"(af[mt][3]), "r"(bf[nt][0]), "r"(bf[nt][1]));
                }
        }
        __syncthreads();
        buf ^= 1;
    }

#pragma unroll
    for (int mt = 0; mt < 2; mt++) {
#pragma unroll
        for (int nt = 0; nt < 4; nt++) {
            int row0 = bm + warp_m * 32 + mt * 16 + lg;
            int col = bn + warp_n * 32 + nt * 8 + 2 * lt;
            if (row0 < N_NODES) {
                float2 v = make_float2(acc[mt][nt][0], acc[mt][nt][1]);
                *(float2*)&g_h[(size_t)row0 * HD + col] = v;
            }
            int row1 = row0 + 8;
            if (row1 < N_NODES) {
                float2 v = make_float2(acc[mt][nt][2], acc[mt][nt][3]);
                *(float2*)&g_h[(size_t)row1 * HD + col] = v;
            }
        }
    }
}

// ------- fused: fp16 convert + per-(node,head) scores (coalesced) --------
__global__ __launch_bounds__(256) void gat_h16score_kernel(
    const float* __restrict__ a) {
    int node = blockIdx.x * 4 + (threadIdx.x >> 6);
    if (node >= N_NODES) return;
    int t = threadIdx.x & 63;
    int head = t >> 4;
    int cih = (t & 15) * 4;   // col within head

    float4 v = *(const float4*)&g_h[(size_t)node * HD + t * 4];

    __half2 h01 = __floats2half2_rn(v.x, v.y);
    __half2 h23 = __floats2half2_rn(v.z, v.w);
    uint2 packed;
    packed.x = *(const uint32_t*)&h01;
    packed.y = *(const uint32_t*)&h23;
    *(uint2*)&g_h16[(size_t)node * HD + t * 4] = packed;

    const float* ah = a + head * (2 * OUT_DIM);
    float4 as = *(const float4*)&ah[cih];
    float4 ad = *(const float4*)&ah[OUT_DIM + cih];
    float ss = v.x * as.x + v.y * as.y + v.z * as.z + v.w * as.w;
    float sd = v.x * ad.x + v.y * ad.y + v.z * ad.z + v.w * ad.w;

#pragma unroll
    for (int off = 8; off >= 1; off >>= 1) {
        ss += __shfl_xor_sync(0xffffffffu, ss, off, 16);
        sd += __shfl_xor_sync(0xffffffffu, sd, off, 16);
    }
    if ((t & 15) == 0) {
        g_ssrc[node * HEADS + head] = ss;
        g_sdst[node * HEADS + head] = sd;
    }
}

// ---------------- zero counters + sums ----------------
__global__ void gat_zero_kernel() {
    int i = blockIdx.x * blockDim.x + threadIdx.x;
    if (i < N_NODES) g_cnt[i] = 0;
    if (i < N_NODES * HEADS) g_sum[i] = 0.f;
}

// ---------------- vector reduction helper ----------------
__device__ __forceinline__ void redAdd4(float* p, float a, float b, float c,
                                        float d) {
    asm volatile("red.global.add.v4.f32 [%0], {%1, %2, %3, %4};" ::
                     "l"(p), "f"(a), "f"(b), "f"(c), "f"(d)
                 : "memory");
}

// ----- fused edge pass: histogram + leaky_relu + exp + segment sum -------
__global__ void gat_edge_kernel(const int* __restrict__ edges) {
    int e = blockIdx.x * blockDim.x + threadIdx.x;
    if (e >= N_EDGES) return;
    int2 ed = ((const int2*)edges)[e];
    float4 ss = *(const float4*)&g_ssrc[ed.x * HEADS];
    float4 sd = *(const float4*)&g_sdst[ed.y * HEADS];
    float4 v;
    v.x = ss.x + sd.x; v.x = (v.x > 0.f) ? v.x : 0.2f * v.x;
    v.y = ss.y + sd.y; v.y = (v.y > 0.f) ? v.y : 0.2f * v.y;
    v.z = ss.z + sd.z; v.z = (v.z > 0.f) ? v.z : 0.2f * v.z;
    v.w = ss.w + sd.w; v.w = (v.w > 0.f) ? v.w : 0.2f * v.w;
    v.x = __expf(v.x);
    v.y = __expf(v.y);
    v.z = __expf(v.z);
    v.w = __expf(v.w);
    *(float4*)&g_e[e * HEADS] = v;
    redAdd4(&g_sum[ed.x * HEADS], v.x, v.y, v.z, v.w);
    atomicAdd(&g_cnt[ed.y], 1);
}

// ---------------- block scan phase 1 ----------------
__global__ void gat_scan1_kernel() {
    __shared__ int s[256];
    int t = threadIdx.x;
    int i = blockIdx.x * 256 + t;
    int v = (i < N_NODES) ? g_cnt[i] : 0;
    s[t] = v;
    __syncthreads();
#pragma unroll
    for (int off = 1; off < 256; off <<= 1) {
        int u = (t >= off) ? s[t - off] : 0;
        __syncthreads();
        s[t] += u;
        __syncthreads();
    }
    if (i < N_NODES) g_offs[i] = s[t] - v;
    if (t == 255) g_part[blockIdx.x] = s[255];
}

// ---------------- scan phase 2 ----------------
__global__ void gat_scan2_kernel(int nblk) {
    __shared__ int s[256];
    int t = threadIdx.x;
    int v = (t < nblk) ? g_part[t] : 0;
    s[t] = v;
    __syncthreads();
#pragma unroll
    for (int off = 1; off < 256; off <<= 1) {
        int u = (t >= off) ? s[t - off] : 0;
        __syncthreads();
        s[t] += u;
        __syncthreads();
    }
    g_part[t] = s[t] - v;
}

// -------- scan phase 3 + reciprocal of denominators (merged) ----------
__global__ void gat_scan3_rsum_kernel() {
    int i = blockIdx.x * blockDim.x + threadIdx.x;
    if (i < N_NODES) {
        g_offs[i] += g_part[i >> 8];
        g_cnt[i] = 0;
    }
    if (i == 0) g_offs[N_NODES] = N_EDGES;
    if (i < N_NODES * HEADS) g_sum[i] = __frcp_rn(g_sum[i] + 1e-10f);
}

// ------- CSR fill + alpha packed as 2x half2 into the entry -----------
__global__ void gat_fill_kernel(const int* __restrict__ edges) {
    int e = blockIdx.x * blockDim.x + threadIdx.x;
    if (e >= N_EDGES) return;
    int2 ed = ((const int2*)edges)[e];
    int pos = g_offs[ed.y] + atomicAdd(&g_cnt[ed.y], 1);
    float4 ex = *(const float4*)&g_e[e * HEADS];
    float4 r = *(const float4*)&g_sum[ed.x * HEADS];
    __half2 a01 = __floats2half2_rn(ex.x * r.x, ex.y * r.y);
    __half2 a23 = __floats2half2_rn(ex.z * r.z, ex.w * r.w);
    int4 entry;
    entry.x = ed.x;
    entry.y = (int)*(const uint32_t*)&a01;
    entry.z = (int)*(const uint32_t*)&a23;
    entry.w = 0;
    g_csr4[pos] = entry;
}

// ------- aggregation: 64 threads/node, 2 LDGs per edge ----------------
__global__ __launch_bounds__(256) void gat_aggregate_kernel(
    float* __restrict__ out, const float* __restrict__ bias) {
    int node = blockIdx.x * 4 + (threadIdx.x >> 6);
    if (node >= N_NODES) return;
    int t = threadIdx.x & 63;     // owns cols [4t, 4t+4)
    int head = t >> 4;

    int beg = g_offs[node];
    int end = g_offs[node + 1];

    float4 acc = make_float4(0.f, 0.f, 0.f, 0.f);

    auto get_alpha = [&](const int4& c) -> float {
        uint32_t sel = (head & 2) ? (uint32_t)c.z : (uint32_t)c.y;
        float2 f = __half22float2(*(const __half2*)&sel);
        return (head & 1) ? f.y : f.x;
    };

    int i = beg;
    for (; i + 3 < end; i += 4) {
        int4 c0 = g_csr4[i];
        int4 c1 = g_csr4[i + 1];
        int4 c2 = g_csr4[i + 2];
        int4 c3 = g_csr4[i + 3];
        uint2 p0 = *(const uint2*)&g_h16[(size_t)c0.x * HD + t * 4];
        uint2 p1 = *(const uint2*)&g_h16[(size_t)c1.x * HD + t * 4];
        uint2 p2 = *(const uint2*)&g_h16[(size_t)c2.x * HD + t * 4];
        uint2 p3 = *(const uint2*)&g_h16[(size_t)c3.x * HD + t * 4];
        float a0 = get_alpha(c0);
        float a1 = get_alpha(c1);
        float a2 = get_alpha(c2);
        float a3 = get_alpha(c3);
        float2 f00 = __half22float2(*(const __half2*)&p0.x);
        float2 f01 = __half22float2(*(const __half2*)&p0.y);
        float2 f10 = __half22float2(*(const __half2*)&p1.x);
        float2 f11 = __half22float2(*(const __half2*)&p1.y);
        float2 f20 = __half22float2(*(const __half2*)&p2.x);
        float2 f21 = __half22float2(*(const __half2*)&p2.y);
        float2 f30 = __half22float2(*(const __half2*)&p3.x);
        float2 f31 = __half22float2(*(const __half2*)&p3.y);
        acc.x += a0 * f00.x + a1 * f10.x + a2 * f20.x + a3 * f30.x;
        acc.y += a0 * f00.y + a1 * f10.y + a2 * f20.y + a3 * f30.y;
        acc.z += a0 * f01.x + a1 * f11.x + a2 * f21.x + a3 * f31.x;
        acc.w += a0 * f01.y + a1 * f11.y + a2 * f21.y + a3 * f31.y;
    }
    for (; i < end; i++) {
        int4 c0 = g_csr4[i];
        uint2 p0 = *(const uint2*)&g_h16[(size_t)c0.x * HD + t * 4];
        float a0 = get_alpha(c0);
        float2 f00 = __half22float2(*(const __half2*)&p0.x);
        float2 f01 = __half22float2(*(const __half2*)&p0.y);
        acc.x += a0 * f00.x;
        acc.y += a0 * f00.y;
        acc.z += a0 * f01.x;
        acc.w += a0 * f01.y;
    }

    float4 b = *(const float4*)&bias[t * 4];
    acc.x += b.x; acc.y += b.y; acc.z += b.z; acc.w += b.w;
    *(float4*)&out[(size_t)node * HD + t * 4] = acc;
}

// ---------------- launch ----------------
extern "C" void kernel_launch(void* const* d_in, const int* in_sizes, int n_in,
                              void* d_out, int out_size) {
    const float* x     = (const float*)d_in[0];
    const int*   edges = (const int*)d_in[1];
    const float* W     = (const float*)d_in[2];
    const float* a     = (const float*)d_in[3];
    const float* bias  = (const float*)d_in[4];
    float* out = (float*)d_out;

    const int nh = N_NODES * HEADS;
    const int nblk_scan = (N_NODES + 255) / 256;  // 196

    gat_zero_kernel<<<(nh + 255) / 256, 256>>>();

    dim3 gemm_grid((N_NODES + GBM - 1) / GBM, HD / GBN);
    gat_gemm_tf32_kernel<<<gemm_grid, 256>>>(x, W);

    gat_h16score_kernel<<<(N_NODES + 3) / 4, 256>>>(a);
    gat_edge_kernel<<<(N_EDGES + 255) / 256, 256>>>(edges);

    gat_scan1_kernel<<<nblk_scan, 256>>>();
    gat_scan2_kernel<<<1, 256>>>(nblk_scan);
    gat_scan3_rsum_kernel<<<(nh + 255) / 256, 256>>>();
    gat_fill_kernel<<<(N_EDGES + 255) / 256, 256>>>(edges);

    gat_aggregate_kernel<<<(N_NODES + 3) / 4, 256>>>(out, bias);
}